// round 3
// baseline (speedup 1.0000x reference)
#include <cuda_runtime.h>
#include <math.h>

#define BATCH 32
#define NTOK 4096
#define DIN 384
#define DS 128
#define NS 8
#define MLPH 256
#define MROWS (BATCH*NTOK)
#define TILE_N 512
#define NT (NTOK/TILE_N)   /* 8 */
#define ATT_SCALE 0.08838834764831845f

// ---------------- scratch (device globals; no allocation) ----------------
__device__ float g_mean[MROWS];
__device__ float g_rstd[MROWS];
__device__ float g_k[MROWS*DS];          // 64 MB
__device__ float g_v[MROWS*DS];          // 64 MB
__device__ float g_slots[BATCH*NS*DS];
__device__ float g_q[BATCH*NS*DS];
__device__ float g_updates[BATCH*NS*DS];
__device__ float g_inv[BATCH*NS];
__device__ float g_psum[BATCH*NT*NS];
__device__ float g_pupd[BATCH*NT*NS*DS];
__device__ int   g_map[BATCH*NS];

__device__ __forceinline__ float warp_sum(float v){
#pragma unroll
    for (int o = 16; o; o >>= 1) v += __shfl_xor_sync(0xffffffffu, v, o);
    return v;
}

// ---------------- kernel 1: per-row LN stats of features ----------------
__global__ void ln_stats_kernel(const float* __restrict__ feat){
    int warp = threadIdx.x >> 5, lane = threadIdx.x & 31;
    int row = blockIdx.x * 8 + warp;
    const float* p = feat + (size_t)row * DIN;
    float s = 0.f, sq = 0.f;
#pragma unroll
    for (int c = 0; c < 3; c++){
        float4 v = *(const float4*)(p + lane*4 + c*128);
        s  += v.x + v.y + v.z + v.w;
        sq += v.x*v.x + v.y*v.y + v.z*v.z + v.w*v.w;
    }
    s = warp_sum(s); sq = warp_sum(sq);
    if (lane == 0){
        float m = s * (1.f/DIN);
        float var = sq * (1.f/DIN) - m*m;
        g_mean[row] = m;
        g_rstd[row] = rsqrtf(var + 1e-5f);
    }
}

// ---------------- kernel 2: fused LN + K/V GEMM  (M=131072,N=128x2,K=384) ----
#define BM 128
#define BN 128
#define BK 16
__global__ void __launch_bounds__(256,2) kv_gemm_kernel(
    const float* __restrict__ feat,
    const float* __restrict__ lng, const float* __restrict__ lnb,
    const float* __restrict__ Wk,  const float* __restrict__ Wv)
{
    __shared__ float As[2][BK][BM+4];
    __shared__ float Bs[2][BK][BN];
    const float* W  = (blockIdx.x == 0) ? Wk : Wv;
    float* out      = (blockIdx.x == 0) ? g_k : g_v;
    int row0 = blockIdx.y * BM;
    int tid = threadIdx.x;
    int tx = tid & 15, ty = tid >> 4;
    int arow  = tid >> 1;
    int acol0 = (tid & 1) * 8;
    float mean = g_mean[row0 + arow];
    float rstd = g_rstd[row0 + arow];
    const float* aptr = feat + (size_t)(row0 + arow) * DIN + acol0;

    float acc[8][8];
#pragma unroll
    for (int i = 0; i < 8; i++)
#pragma unroll
        for (int j = 0; j < 8; j++) acc[i][j] = 0.f;

    float4 aA0, aA1, bB0, bB1, gA0, gA1, cA0, cA1;

    auto loadg = [&](int k0){
        aA0 = *(const float4*)(aptr + k0);
        aA1 = *(const float4*)(aptr + k0 + 4);
        gA0 = *(const float4*)(lng + k0 + acol0);
        gA1 = *(const float4*)(lng + k0 + acol0 + 4);
        cA0 = *(const float4*)(lnb + k0 + acol0);
        cA1 = *(const float4*)(lnb + k0 + acol0 + 4);
        int i0 = tid, i1 = tid + 256;
        bB0 = *(const float4*)(W + (size_t)(k0 + (i0>>5))*DS + (i0&31)*4);
        bB1 = *(const float4*)(W + (size_t)(k0 + (i1>>5))*DS + (i1&31)*4);
    };
    auto stores = [&](int buf){
        float av[8] = {aA0.x,aA0.y,aA0.z,aA0.w,aA1.x,aA1.y,aA1.z,aA1.w};
        float gv[8] = {gA0.x,gA0.y,gA0.z,gA0.w,gA1.x,gA1.y,gA1.z,gA1.w};
        float cv[8] = {cA0.x,cA0.y,cA0.z,cA0.w,cA1.x,cA1.y,cA1.z,cA1.w};
#pragma unroll
        for (int j = 0; j < 8; j++)
            As[buf][acol0 + j][arow] = (av[j] - mean) * rstd * gv[j] + cv[j];
        int i0 = tid, i1 = tid + 256;
        *(float4*)&Bs[buf][i0>>5][(i0&31)*4] = bB0;
        *(float4*)&Bs[buf][i1>>5][(i1&31)*4] = bB1;
    };

    loadg(0); stores(0); __syncthreads();
    const int nk = DIN / BK;   // 24
    for (int t = 0; t < nk; t++){
        int cur = t & 1;
        if (t + 1 < nk) loadg((t+1)*BK);
#pragma unroll
        for (int kk = 0; kk < BK; kk++){
            float4 a0 = *(const float4*)&As[cur][kk][ty*8];
            float4 a1 = *(const float4*)&As[cur][kk][ty*8+4];
            float4 b0 = *(const float4*)&Bs[cur][kk][tx*8];
            float4 b1 = *(const float4*)&Bs[cur][kk][tx*8+4];
            float ar[8] = {a0.x,a0.y,a0.z,a0.w,a1.x,a1.y,a1.z,a1.w};
            float br[8] = {b0.x,b0.y,b0.z,b0.w,b1.x,b1.y,b1.z,b1.w};
#pragma unroll
            for (int i = 0; i < 8; i++)
#pragma unroll
                for (int j = 0; j < 8; j++) acc[i][j] += ar[i]*br[j];
        }
        if (t + 1 < nk){ stores((t+1)&1); __syncthreads(); }
    }
#pragma unroll
    for (int i = 0; i < 8; i++){
        float* op = out + (size_t)(row0 + ty*8 + i) * DS + tx*8;
        float4 o0 = {acc[i][0],acc[i][1],acc[i][2],acc[i][3]};
        float4 o1 = {acc[i][4],acc[i][5],acc[i][6],acc[i][7]};
        *(float4*)op = o0; *(float4*)(op+4) = o1;
    }
}

// ---------------- kernel 3: slot init from slot_mu ----------------
__global__ void init_slots_kernel(const float* __restrict__ mu){
    int i = blockIdx.x * blockDim.x + threadIdx.x;
    if (i < BATCH*NS*DS) g_slots[i] = mu[i & (DS-1)];
}

// ---------------- kernel 4: LN(slots) @ Wq ----------------
__global__ void compute_q_kernel(const float* __restrict__ Wq,
                                 const float* __restrict__ gg,
                                 const float* __restrict__ bb){
    __shared__ float sl[NS][DS];
    __shared__ float sn[NS][DS];
    int b = blockIdx.x, tid = threadIdx.x;
#pragma unroll
    for (int l = 0; l < 4; l++){
        int o = l*256 + tid;
        sl[o>>7][o&127] = g_slots[b*NS*DS + o];
    }
    __syncthreads();
    int w = tid >> 5, lane = tid & 31;
    {
        float4 x = *(float4*)&sl[w][lane*4];
        float s  = x.x + x.y + x.z + x.w;
        float sq = x.x*x.x + x.y*x.y + x.z*x.z + x.w*x.w;
        s = warp_sum(s); sq = warp_sum(sq);
        float m = s * (1.f/DS);
        float var = sq * (1.f/DS) - m*m;
        float r = rsqrtf(var + 1e-5f);
        int e = lane*4;
        sn[w][e+0] = (x.x-m)*r*gg[e+0] + bb[e+0];
        sn[w][e+1] = (x.y-m)*r*gg[e+1] + bb[e+1];
        sn[w][e+2] = (x.z-m)*r*gg[e+2] + bb[e+2];
        sn[w][e+3] = (x.w-m)*r*gg[e+3] + bb[e+3];
    }
    __syncthreads();
#pragma unroll
    for (int l = 0; l < 4; l++){
        int o = l*256 + tid; int s = o >> 7, d = o & 127;
        float acc = 0.f;
        for (int e = 0; e < DS; e++) acc += sn[s][e] * Wq[e*DS + d];
        g_q[b*NS*DS + o] = acc;
    }
}

// ---------------- kernel 5: logits + softmax-over-slots + attn write + partial slot sums
__global__ void __launch_bounds__(256) logits_kernel(float* __restrict__ attn_out){
    __shared__ float at[NS][TILE_N];
    __shared__ float wsum[8][NS];
    int nt = blockIdx.x, b = blockIdx.y;
    int tid = threadIdx.x, w = tid >> 5, lane = tid & 31;
    int n0 = nt * TILE_N;
    float4 q[NS];
#pragma unroll
    for (int s = 0; s < NS; s++)
        q[s] = *(const float4*)&g_q[(b*NS + s)*DS + lane*4];
    float rs[NS] = {0,0,0,0,0,0,0,0};
    for (int j = 0; j < TILE_N/8; j++){
        int n = n0 + w*64 + j;
        float4 kv = *(const float4*)&g_k[(size_t)(b*NTOK + n)*DS + lane*4];
        float p[NS];
#pragma unroll
        for (int s = 0; s < NS; s++)
            p[s] = kv.x*q[s].x + kv.y*q[s].y + kv.z*q[s].z + kv.w*q[s].w;
#pragma unroll
        for (int o = 16; o; o >>= 1)
#pragma unroll
            for (int s = 0; s < NS; s++) p[s] += __shfl_xor_sync(0xffffffffu, p[s], o);
        float mx = -1e30f;
#pragma unroll
        for (int s = 0; s < NS; s++){ p[s] *= ATT_SCALE; mx = fmaxf(mx, p[s]); }
        float tot = 0.f;
#pragma unroll
        for (int s = 0; s < NS; s++){ p[s] = expf(p[s] - mx); tot += p[s]; }
        float itot = 1.f / tot;
#pragma unroll
        for (int s = 0; s < NS; s++){
            float a = p[s] * itot;
            rs[s] += a;
            if (lane == s) at[s][w*64 + j] = a;
        }
    }
    if (lane == 0){
#pragma unroll
        for (int s = 0; s < NS; s++) wsum[w][s] = rs[s];
    }
    __syncthreads();
    if (tid < NS){
        float acc = 0.f;
#pragma unroll
        for (int ww = 0; ww < 8; ww++) acc += wsum[ww][tid];
        g_psum[(b*NT + nt)*NS + tid] = acc;
    }
#pragma unroll
    for (int l = 0; l < 16; l++){
        int o = l*256 + tid; int s = o >> 9, jj = o & 511;
        attn_out[(size_t)(b*NS + s)*NTOK + n0 + jj] = at[s][jj];
    }
}

// ---------------- kernel 6: reduce slot sums, compute 1/(sum+eps) ----------------
__global__ void reduce_sums_kernel(){
    int t = threadIdx.x;               // 256 = 32*8
    int b = t >> 3, s = t & 7;
    float acc = 0.f;
#pragma unroll
    for (int nt = 0; nt < NT; nt++) acc += g_psum[(b*NT + nt)*NS + s];
    g_inv[t] = 1.f / (acc + 1e-8f);
}

// ---------------- kernel 7: partial updates = attn_norm @ v ----------------
__global__ void __launch_bounds__(256) upd_partial_kernel(const float* __restrict__ attn_out){
    __shared__ float at[NS][TILE_N];
    __shared__ float inv[NS];
    int nt = blockIdx.x, b = blockIdx.y, tid = threadIdx.x;
    int n0 = nt * TILE_N;
    if (tid < NS) inv[tid] = g_inv[b*NS + tid];
    __syncthreads();
#pragma unroll
    for (int l = 0; l < 16; l++){
        int o = l*256 + tid; int s = o >> 9, jj = o & 511;
        at[s][jj] = attn_out[(size_t)(b*NS + s)*NTOK + n0 + jj] * inv[s];
    }
    __syncthreads();
    int d = tid & 127, sg = tid >> 7;
    float acc[4] = {0,0,0,0};
    const float* vp = g_v + (size_t)(b*NTOK + n0)*DS + d;
    for (int n = 0; n < TILE_N; n++){
        float vv = vp[(size_t)n*DS];
#pragma unroll
        for (int i = 0; i < 4; i++) acc[i] += at[sg*4 + i][n] * vv;
    }
#pragma unroll
    for (int i = 0; i < 4; i++)
        g_pupd[((b*NT + nt)*NS + sg*4 + i)*DS + d] = acc[i];
}

// ---------------- kernel 8: reduce partial updates ----------------
__global__ void reduce_updates_kernel(){
    int b = blockIdx.x, tid = threadIdx.x;
#pragma unroll
    for (int l = 0; l < 4; l++){
        int o = l*256 + tid;
        float acc = 0.f;
#pragma unroll
        for (int nt = 0; nt < NT; nt++) acc += g_pupd[(b*NT + nt)*1024 + o];
        g_updates[b*1024 + o] = acc;
    }
}

// ---------------- kernel 9: GRU + LN + MLP residual (per batch) ----------------
__global__ void __launch_bounds__(256) slot_update_kernel(
    const float* __restrict__ W_ih, const float* __restrict__ W_hh,
    const float* __restrict__ b_ih, const float* __restrict__ b_hh,
    const float* __restrict__ lmg,  const float* __restrict__ lmb,
    const float* __restrict__ W1,   const float* __restrict__ b1,
    const float* __restrict__ W2,   const float* __restrict__ b2)
{
    __shared__ float buf[9216];
    float* xs  = buf;            // [8][128] updates
    float* hs  = buf + 1024;     // [8][128] prev slots
    float* gx  = buf + 2048;     // [8][384]
    float* gh  = buf + 5120;     // [8][384]
    float* sn  = buf + 8192;     // [8][128] post-GRU slots
    float* hl  = buf;            // reuse xs region: LN output [8][128]
    float* hid = buf + 2048;     // reuse gx region: MLP hidden [8][256]
    int b = blockIdx.x, tid = threadIdx.x;
#pragma unroll
    for (int l = 0; l < 8; l++){
        int o = l*256 + tid;
        if (o < 1024){ } // (always true: 8*256=2048 > 1024 handled below)
    }
#pragma unroll
    for (int l = 0; l < 4; l++){
        int o = l*256 + tid;
        xs[o] = g_updates[b*1024 + o];
        hs[o] = g_slots[b*1024 + o];
    }
    __syncthreads();
    // gx/gh: [8][384] = x@W_ih^T + b_ih,  h@W_hh^T + b_hh
    for (int j = tid; j < 384; j += 256){
        float ax[8] = {0,0,0,0,0,0,0,0};
        float ah[8] = {0,0,0,0,0,0,0,0};
        const float4* wx = (const float4*)(W_ih + (size_t)j*DS);
        const float4* wh = (const float4*)(W_hh + (size_t)j*DS);
        for (int d4 = 0; d4 < 32; d4++){
            float4 wxv = wx[d4], whv = wh[d4];
            int d = d4*4;
#pragma unroll
            for (int i = 0; i < 8; i++){
                float4 xv = *(const float4*)&xs[i*DS + d];
                float4 hv = *(const float4*)&hs[i*DS + d];
                ax[i] += xv.x*wxv.x + xv.y*wxv.y + xv.z*wxv.z + xv.w*wxv.w;
                ah[i] += hv.x*whv.x + hv.y*whv.y + hv.z*whv.z + hv.w*whv.w;
            }
        }
        float bi = b_ih[j], bh = b_hh[j];
#pragma unroll
        for (int i = 0; i < 8; i++){
            gx[i*384 + j] = ax[i] + bi;
            gh[i*384 + j] = ah[i] + bh;
        }
    }
    __syncthreads();
    // GRU gates
#pragma unroll
    for (int l = 0; l < 4; l++){
        int o = l*256 + tid; int i = o >> 7, jj = o & 127;
        float r  = 1.f/(1.f + expf(-(gx[i*384 + jj]       + gh[i*384 + jj])));
        float z  = 1.f/(1.f + expf(-(gx[i*384 + 128 + jj] + gh[i*384 + 128 + jj])));
        float nn = tanhf(gx[i*384 + 256 + jj] + r * gh[i*384 + 256 + jj]);
        sn[o] = (1.f - z)*nn + z*hs[o];
    }
    __syncthreads();
    // LN(sn) -> hl  (warp per slot row)
    {
        int w = tid >> 5, lane = tid & 31;
        float4 x = *(float4*)&sn[w*DS + lane*4];
        float s  = x.x + x.y + x.z + x.w;
        float sq = x.x*x.x + x.y*x.y + x.z*x.z + x.w*x.w;
        s = warp_sum(s); sq = warp_sum(sq);
        float m = s * (1.f/DS);
        float var = sq * (1.f/DS) - m*m;
        float r = rsqrtf(var + 1e-5f);
        int e = lane*4;
        hl[w*DS + e+0] = (x.x-m)*r*lmg[e+0] + lmb[e+0];
        hl[w*DS + e+1] = (x.y-m)*r*lmg[e+1] + lmb[e+1];
        hl[w*DS + e+2] = (x.z-m)*r*lmg[e+2] + lmb[e+2];
        hl[w*DS + e+3] = (x.w-m)*r*lmg[e+3] + lmb[e+3];
    }
    __syncthreads();
    // hidden = silu(hl @ W1 + b1)
    {
        int m = tid;  // 0..255
        float acc[8] = {0,0,0,0,0,0,0,0};
        for (int d = 0; d < DS; d++){
            float w1 = W1[(size_t)d*MLPH + m];
#pragma unroll
            for (int i = 0; i < 8; i++) acc[i] += hl[i*DS + d] * w1;
        }
        float c1 = b1[m];
#pragma unroll
        for (int i = 0; i < 8; i++){
            float h = acc[i] + c1;
            hid[i*MLPH + m] = h / (1.f + expf(-h));   // silu
        }
    }
    __syncthreads();
    // slots = sn + hidden @ W2 + b2
    {
        int d = tid & 127, ig = tid >> 7;
        float acc[4] = {0,0,0,0};
        for (int m = 0; m < MLPH; m++){
            float w2 = W2[(size_t)m*DS + d];
#pragma unroll
            for (int ii = 0; ii < 4; ii++) acc[ii] += hid[(ig*4 + ii)*MLPH + m] * w2;
        }
        float c2 = b2[d];
#pragma unroll
        for (int ii = 0; ii < 4; ii++){
            int i = ig*4 + ii;
            g_slots[b*1024 + i*DS + d] = sn[i*DS + d] + acc[ii] + c2;
        }
    }
}

// ---------------- kernel 10: greedy merge map (warp per batch) ----------------
__global__ void merge_map_kernel(float* __restrict__ mm_out){
    __shared__ float sn[NS][DS];
    __shared__ float sim[64];
    int b = blockIdx.x, lane = threadIdx.x;
#pragma unroll
    for (int s = 0; s < NS; s++){
        float4 v = *(const float4*)&g_slots[b*1024 + s*DS + lane*4];
        float sq = v.x*v.x + v.y*v.y + v.z*v.z + v.w*v.w;
        sq = warp_sum(sq);
        float invn = 1.f / fmaxf(sqrtf(sq), 1e-12f);
        int e = lane*4;
        sn[s][e+0] = v.x*invn; sn[s][e+1] = v.y*invn;
        sn[s][e+2] = v.z*invn; sn[s][e+3] = v.w*invn;
    }
    __syncwarp();
    for (int p = lane; p < 64; p += 32){
        int s1 = p >> 3, s2 = p & 7;
        float acc = 0.f;
        for (int e = 0; e < DS; e++) acc += sn[s1][e] * sn[s2][e];
        sim[p] = acc - (s1 == s2 ? 2.f : 0.f);
    }
    __syncwarp();
    if (lane == 0){
        int mt[8] = {0,1,2,3,4,5,6,7};
        for (int rd = 0; rd < NS; rd++){
            float best = -1e30f; int bi = 0;
            for (int idx = 0; idx < 64; idx++)
                if (sim[idx] > best){ best = sim[idx]; bi = idx; }
            int row = bi >> 3, col = bi & 7;
            if (best > 0.9f){
                int src = row > col ? row : col;
                int tgt = row < col ? row : col;
                mt[src] = tgt;
                for (int t = 0; t < 8; t++){ sim[src*8 + t] = -2.f; sim[t*8 + src] = -2.f; }
            }
        }
        for (int s = 0; s < NS; s++){
            g_map[b*NS + s] = mt[s];
            mm_out[b*NS + s] = (float)mt[s];
        }
    }
}

// ---------------- kernel 11: merged slots (segment mean) + raw out ----------------
__global__ void merged_kernel(float* __restrict__ merged_out, float* __restrict__ raw_out){
    int b = blockIdx.x, d = threadIdx.x;   // 128 threads
    int mp[8];
#pragma unroll
    for (int s = 0; s < 8; s++) mp[s] = g_map[b*NS + s];
    float rv[8];
#pragma unroll
    for (int s = 0; s < 8; s++){
        rv[s] = g_slots[b*1024 + s*DS + d];
        raw_out[b*1024 + s*DS + d] = rv[s];
    }
#pragma unroll
    for (int t = 0; t < 8; t++){
        float sum = 0.f, c = 0.f;
#pragma unroll
        for (int s = 0; s < 8; s++)
            if (mp[s] == t){ sum += rv[s]; c += 1.f; }
        merged_out[b*1024 + t*DS + d] = sum / fmaxf(c, 1.f);
    }
}

// ---------------- launcher ----------------
extern "C" void kernel_launch(void* const* d_in, const int* in_sizes, int n_in,
                              void* d_out, int out_size)
{
    const float* feat    = (const float*)d_in[0];
    const float* ln_in_g = (const float*)d_in[1];
    const float* ln_in_b = (const float*)d_in[2];
    const float* Wk      = (const float*)d_in[3];
    const float* Wv      = (const float*)d_in[4];
    const float* Wq      = (const float*)d_in[5];
    const float* ln_s_g  = (const float*)d_in[6];
    const float* ln_s_b  = (const float*)d_in[7];
    const float* W_ih    = (const float*)d_in[8];
    const float* W_hh    = (const float*)d_in[9];
    const float* b_ih    = (const float*)d_in[10];
    const float* b_hh    = (const float*)d_in[11];
    const float* ln_m_g  = (const float*)d_in[12];
    const float* ln_m_b  = (const float*)d_in[13];
    const float* W1      = (const float*)d_in[14];
    const float* b1      = (const float*)d_in[15];
    const float* W2      = (const float*)d_in[16];
    const float* b2      = (const float*)d_in[17];
    const float* slot_mu = (const float*)d_in[18];

    float* out        = (float*)d_out;
    float* merged_out = out;                               // [32,8,128]
    float* attn_out   = out + BATCH*NS*DS;                 // [32,8,4096]
    float* mm_out     = attn_out + (size_t)BATCH*NS*NTOK;  // [32,8]
    float* raw_out    = mm_out + BATCH*NS;                 // [32,8,128]

    ln_stats_kernel<<<MROWS/8, 256>>>(feat);
    kv_gemm_kernel<<<dim3(2, MROWS/BM), 256>>>(feat, ln_in_g, ln_in_b, Wk, Wv);
    init_slots_kernel<<<(BATCH*NS*DS + 255)/256, 256>>>(slot_mu);

    for (int it = 0; it < 3; it++){
        compute_q_kernel<<<BATCH, 256>>>(Wq, ln_s_g, ln_s_b);
        logits_kernel<<<dim3(NT, BATCH), 256>>>(attn_out);
        reduce_sums_kernel<<<1, 256>>>();
        upd_partial_kernel<<<dim3(NT, BATCH), 256>>>(attn_out);
        reduce_updates_kernel<<<BATCH, 256>>>();
        slot_update_kernel<<<BATCH, 256>>>(W_ih, W_hh, b_ih, b_hh,
                                           ln_m_g, ln_m_b, W1, b1, W2, b2);
    }
    merge_map_kernel<<<BATCH, 32>>>(mm_out);
    merged_kernel<<<BATCH, 128>>>(merged_out, raw_out);
}